// round 6
// baseline (speedup 1.0000x reference)
#include <cuda_runtime.h>
#include <cuda_bf16.h>
#include <cstdint>

// ---------------------------------------------------------------------------
// SupConLossWithQueue:  Q=4096, bsz=256, B=4352, 2B=8704, D=128, T=0.07
// rows g in [3841,8193). log_prob = d/T - log(sum_{lab!=} exp(d/T)); row-max
// cancels; d/T<=14.3 so fp32 sum-exp is safe without max tracking.
// NOTE: bench targets plain sm_100 -> NO tcgen05. HMMA (mma.sync) path.
// ---------------------------------------------------------------------------
#define Qn      4096
#define BSZh    256
#define Bn      4352
#define N2      8704
#define Dk      128
#define ROW0    3841
#define NR      4352
#define NCLS    100
#define MAXP    512
#define NQ      4
#define COLQ    2176
#define NTILE   17
#define KRB     34
#define INV_T   14.2857142857142857f

__device__ __nv_bfloat16 g_cB[N2][Dk];
__device__ int           g_lab[N2];
__device__ int           g_pk[N2];          // (rank<<16)|label
__device__ int           g_clsOff[NCLS + 1];
__device__ float         g_rowZ[NR][NQ];
__device__ float         g_posD[NR * MAXP];
__device__ float         g_blkSum[KRB];
__device__ unsigned int  g_ctr;

// ---------------------------------------------------------------------------
__device__ __forceinline__ void mma16816(float* c, const uint32_t* a, uint32_t b0, uint32_t b1)
{
    asm volatile(
        "mma.sync.aligned.m16n8k16.row.col.f32.bf16.bf16.f32 "
        "{%0,%1,%2,%3}, {%4,%5,%6,%7}, {%8,%9}, {%0,%1,%2,%3};\n"
        : "+f"(c[0]), "+f"(c[1]), "+f"(c[2]), "+f"(c[3])
        : "r"(a[0]), "r"(a[1]), "r"(a[2]), "r"(a[3]), "r"(b0), "r"(b1));
}

// cp.async one tile: 128 rows x 256B into padded-272B-stride smem
__device__ __forceinline__ void load_tile_async(uint32_t dstbase, int srcrow, int tid)
{
#pragma unroll
    for (int i = 0; i < 8; i++) {
        int cid = tid + i * 256;
        int row = cid >> 4, ch = cid & 15;
        asm volatile("cp.async.cg.shared.global [%0], [%1], 16;\n"
                     :: "r"(dstbase + (uint32_t)(row * 272 + ch * 16)),
                        "l"((const void*)(&g_cB[srcrow + row][ch * 8])) : "memory");
    }
}

// ---------------------------------------------------------------------------
// Kernel P: gather contrast rows (bf16) + labels; extra block does buckets
// ---------------------------------------------------------------------------
__device__ __forceinline__ int lab_of(int c, const int* label, const int* lq)
{
    int i = (c >= Bn) ? c - Bn : c;
    return (i < BSZh) ? label[i] : ((i < Qn) ? lq[i] : label[i - Qn]);
}

__global__ void __launch_bounds__(256) kprep(const float* __restrict__ feat,
                                             const int*   __restrict__ label,
                                             const float* __restrict__ fq,
                                             const float* __restrict__ fq2,
                                             const int*   __restrict__ lq)
{
    if (blockIdx.x == 1088) {     // ---- bucket block ----
        __shared__ int scnt[NCLS], soff[NCLS + 1];
        int tid = threadIdx.x;
        if (tid < NCLS) scnt[tid] = 0;
        __syncthreads();
        for (int c = tid; c < N2; c += 256) atomicAdd(&scnt[lab_of(c, label, lq)], 1);
        __syncthreads();
        if (tid == 0) {
            int run = 0;
            for (int k = 0; k < NCLS; k++) { soff[k] = run; run += scnt[k]; }
            soff[NCLS] = run;
            g_ctr = 0u;
        }
        __syncthreads();
        if (tid <= NCLS) g_clsOff[tid] = soff[tid];
        if (tid < NCLS)  scnt[tid] = 0;
        __syncthreads();
        for (int c = tid; c < N2; c += 256) {
            int l = lab_of(c, label, lq);
            int rank = atomicAdd(&scnt[l], 1);
            g_pk[c] = l | (rank << 16);
        }
        return;
    }

    int gid = blockIdx.x * 256 + threadIdx.x;
    int c = gid >> 5, q = gid & 31;
    int half = (c >= Bn) ? 1 : 0;
    int i = c - half * Bn;

    const float* src;
    if (i < BSZh)      src = feat + (half ? i : (BSZh + i)) * Dk;
    else if (i < Qn)   src = (half ? fq2 : fq) + i * Dk;
    else               src = feat + ((half ? BSZh : 0) + (i - Qn)) * Dk;

    float4 v = *(const float4*)(src + q * 4);
    __nv_bfloat162 b01, b23;
    b01.x = __float2bfloat16(v.x); b01.y = __float2bfloat16(v.y);
    b23.x = __float2bfloat16(v.z); b23.y = __float2bfloat16(v.w);
    *(__nv_bfloat162*)(&g_cB[c][q * 4])     = b01;
    *(__nv_bfloat162*)(&g_cB[c][q * 4 + 2]) = b23;
    if (q == 0) g_lab[c] = lab_of(c, label, lq);
}

// ---------------------------------------------------------------------------
// Kernel G: HMMA GEMM, M-tile 128 x N-quarter 2176, K=128.
// Warp tile M=32 x N=64 (warp grid 4x2). cp.async double-buffered B.
// Fused masked sum-of-exp + dense positive scatter. grid (34,4) x 256 thr.
// ---------------------------------------------------------------------------
#define SM_A   0                       // 128*272 = 34816
#define SM_B0  34816
#define SM_B1  69632
#define SM_PK  104448                  // 2176*4  = 8704
#define SM_Z   113152                  // 256*4   = 1024
#define SMEM_BYTES 114176

__global__ void __launch_bounds__(256) kgemm()
{
    extern __shared__ __align__(16) unsigned char sm[];
    const uint32_t smem_base = (uint32_t)__cvta_generic_to_shared(sm);
    int*   sPk = (int*)(sm + SM_PK);
    float* sZf = (float*)(sm + SM_Z);

    const int tid = threadIdx.x, lane = tid & 31, wid = tid >> 5;
    const int wm = wid >> 1;       // 0..3 : rows wm*32..+31
    const int wn = wid & 1;        // 0..1 : cols wn*64..+63
    const int rowbase = blockIdx.x * 128;
    const int colbase = blockIdx.y * COLQ;

    // prologue: A + B0 (group0), B1 (group1), pk table
    load_tile_async(smem_base + SM_A,  ROW0 + rowbase, tid);
    load_tile_async(smem_base + SM_B0, colbase, tid);
    asm volatile("cp.async.commit_group;\n" ::: "memory");
    load_tile_async(smem_base + SM_B1, colbase + 128, tid);
    asm volatile("cp.async.commit_group;\n" ::: "memory");
    for (int i = tid; i < COLQ; i += 256) sPk[i] = g_pk[colbase + i];

    // row labels for this thread's 4 accumulator rows
    const int rbase = rowbase + wm * 32 + (lane >> 2);
    int rl[4];
    float zr[4] = {0.f, 0.f, 0.f, 0.f};
#pragma unroll
    for (int j = 0; j < 4; j++) rl[j] = g_lab[ROW0 + rbase + j * 8];

    asm volatile("cp.async.wait_group 1;\n" ::: "memory");
    __syncthreads();

    // preload all A fragments: 8 k-steps x 2 m16-frags x 4 regs
    uint32_t afr[8][2][4];
    {
        uint32_t abase = smem_base + SM_A;
        uint32_t a0 = abase + (wm * 32 + (lane & 15)) * 272 + ((lane >> 4) << 4);
#pragma unroll
        for (int ks = 0; ks < 8; ks++) {
#pragma unroll
            for (int mf = 0; mf < 2; mf++) {
                uint32_t a = a0 + mf * (16 * 272) + ks * 32;
                asm volatile("ldmatrix.sync.aligned.m8n8.x4.shared.b16 {%0,%1,%2,%3}, [%4];"
                             : "=r"(afr[ks][mf][0]), "=r"(afr[ks][mf][1]),
                               "=r"(afr[ks][mf][2]), "=r"(afr[ks][mf][3])
                             : "r"(a));
            }
        }
    }

    const int bj = lane >> 3;
    const int bn_off = ((bj & 2) << 2) + (lane & 7);
    const uint32_t bk_off = (uint32_t)((bj & 1) << 4);

    for (int t = 0; t < NTILE; t++) {
        const uint32_t bbase = smem_base + ((t & 1) ? SM_B1 : SM_B0);

        // MMA: 32(M) x 64(N) per warp, K=128
        float acc[2][8][4] = {};
#pragma unroll
        for (int ks = 0; ks < 8; ks++) {
#pragma unroll
            for (int gix = 0; gix < 4; gix++) {
                uint32_t ba = bbase + (uint32_t)((wn * 64 + gix * 16 + bn_off) * 272)
                              + (uint32_t)(ks * 32) + bk_off;
                uint32_t b0, b1, b2, b3;
                asm volatile("ldmatrix.sync.aligned.m8n8.x4.shared.b16 {%0,%1,%2,%3}, [%4];"
                             : "=r"(b0), "=r"(b1), "=r"(b2), "=r"(b3) : "r"(ba));
#pragma unroll
                for (int mf = 0; mf < 2; mf++) {
                    mma16816(acc[mf][2 * gix],     afr[ks][mf], b0, b1);
                    mma16816(acc[mf][2 * gix + 1], afr[ks][mf], b2, b3);
                }
            }
        }

        // epilogue: masked sum-of-exp + positive-logit scatter
        const int cb = t * 128 + wn * 64 + 2 * (lane & 3);
#pragma unroll
        for (int mf = 0; mf < 2; mf++) {
            const int r0 = rbase + mf * 16;
            const int z0i = mf * 2;
#pragma unroll
            for (int nf = 0; nf < 8; nf++) {
                int2 pk = *(const int2*)&sPk[cb + nf * 8];
                int l0 = pk.x & 0xffff, l1 = pk.y & 0xffff;
                float x00 = acc[mf][nf][0] * INV_T, x01 = acc[mf][nf][1] * INV_T;
                float x10 = acc[mf][nf][2] * INV_T, x11 = acc[mf][nf][3] * INV_T;
                bool e00 = (l0 == rl[z0i]),     e01 = (l1 == rl[z0i]);
                bool e10 = (l0 == rl[z0i + 1]), e11 = (l1 == rl[z0i + 1]);
                zr[z0i]     += __expf(e00 ? -2e30f : x00) + __expf(e01 ? -2e30f : x01);
                zr[z0i + 1] += __expf(e10 ? -2e30f : x10) + __expf(e11 ? -2e30f : x11);
                if (e00) g_posD[r0 * MAXP + (pk.x >> 16)] = x00;
                if (e01) g_posD[r0 * MAXP + (pk.y >> 16)] = x01;
                if (e10) g_posD[(r0 + 8) * MAXP + (pk.x >> 16)] = x10;
                if (e11) g_posD[(r0 + 8) * MAXP + (pk.y >> 16)] = x11;
            }
        }

        __syncthreads();   // all warps done reading buf[t&1]
        if (t < NTILE - 2) {
            load_tile_async(smem_base + ((t & 1) ? SM_B1 : SM_B0),
                            colbase + (t + 2) * 128, tid);
            asm volatile("cp.async.commit_group;\n" ::: "memory");
            asm volatile("cp.async.wait_group 1;\n" ::: "memory");
        } else if (t == NTILE - 2) {
            asm volatile("cp.async.wait_group 0;\n" ::: "memory");
        }
        if (t < NTILE - 1) __syncthreads();
    }

    // reduce z across the 4 lanes (lane&3) sharing each row
#pragma unroll
    for (int j = 0; j < 4; j++) {
        zr[j] += __shfl_xor_sync(0xffffffffu, zr[j], 1);
        zr[j] += __shfl_xor_sync(0xffffffffu, zr[j], 2);
    }
    if ((lane & 3) == 0) {
        int rb = wm * 32 + (lane >> 2);
#pragma unroll
        for (int j = 0; j < 4; j++) sZf[wn * 128 + rb + j * 8] = zr[j];
    }
    __syncthreads();
    if (tid < 128)
        g_rowZ[rowbase + tid][blockIdx.y] = sZf[tid] + sZf[128 + tid];
}

// ---------------------------------------------------------------------------
// Kernel R: thread per row over dense positives + fused final mean
// ---------------------------------------------------------------------------
__global__ void __launch_bounds__(128) krow(float* __restrict__ out)
{
    __shared__ float sr[128];
    __shared__ bool amLast;

    int tid = threadIdx.x;
    int w = blockIdx.x * 128 + tid;
    int g = ROW0 + w;
    int rl = g_lab[g];
    bool exc = (g < Bn) || (g == 8192);
    int cnt = g_clsOff[rl + 1] - g_clsOff[rl];
    int selfRank = g_pk[g] >> 16;

    float4 zz = *(const float4*)g_rowZ[w];
    float lse = __logf((zz.x + zz.y) + (zz.z + zz.w));

    float s = 0.f;
    const float* pd = &g_posD[w * MAXP];
#pragma unroll 4
    for (int i = 0; i < cnt; i++) {
        float x = pd[i];
        if (!(exc && i == selfRank)) s += fminf(0.f, x - lse);
    }
    sr[tid] = s / (float)(cnt - (exc ? 1 : 0));
    __syncthreads();
    for (int st = 64; st; st >>= 1) {
        if (tid < st) sr[tid] += sr[tid + st];
        __syncthreads();
    }
    if (tid == 0) {
        g_blkSum[blockIdx.x] = sr[0];
        __threadfence();
        amLast = (atomicAdd(&g_ctr, 1u) == gridDim.x - 1);
    }
    __syncthreads();
    if (amLast && tid == 0) {
        float a = 0.f;
#pragma unroll
        for (int i = 0; i < KRB; i++) a += g_blkSum[i];
        float loss = -(a / (float)NR);
        out[0] = loss; out[1] = loss; out[2] = loss;
    }
}

// ---------------------------------------------------------------------------
extern "C" void kernel_launch(void* const* d_in, const int* in_sizes, int n_in,
                              void* d_out, int out_size)
{
    const float* feat  = (const float*)d_in[0];
    const int*   label = (const int*)d_in[1];
    const float* fq    = (const float*)d_in[2];
    const float* fq2   = (const float*)d_in[3];
    const int*   lq    = (const int*)d_in[4];
    float* out = (float*)d_out;

    cudaFuncSetAttribute(kgemm, cudaFuncAttributeMaxDynamicSharedMemorySize, SMEM_BYTES);

    kprep<<<1089, 256>>>(feat, label, fq, fq2, lq);
    kgemm<<<dim3(NR / 128, NQ), 256, SMEM_BYTES>>>();
    krow<<<KRB, 128>>>(out);
}

// round 7
// speedup vs baseline: 1.0253x; 1.0253x over previous
#include <cuda_runtime.h>
#include <cuda_bf16.h>
#include <cstdint>

// ---------------------------------------------------------------------------
// SupConLossWithQueue:  Q=4096, bsz=256, B=4352, 2B=8704, D=128, T=0.07
// rows g in [3841,8193). log_prob = d/T - log(sum_{lab!=} exp(d/T)); row-max
// cancels; d/T<=14.3 so fp32 sum-exp is safe without max tracking.
// plain sm_100 target -> HMMA (mma.sync) + cp.async only.
// ---------------------------------------------------------------------------
#define Qn      4096
#define BSZh    256
#define Bn      4352
#define N2      8704
#define Dk      128
#define ROW0    3841
#define NR      4352
#define NCLS    100
#define MAXP    512
#define NQ      4
#define COLQ    2176
#define NTILE   17
#define KRB     34
#define INV_T   14.2857142857142857f

__device__ __nv_bfloat16 g_cB[N2][Dk];
__device__ int           g_lab[N2];
__device__ int           g_pk[N2];          // (rank<<16)|label
__device__ int           g_clsOff[NCLS + 1];
__device__ float         g_rowZ[NR][NQ];
__device__ float         g_posD[NR * MAXP];
__device__ float         g_blkSum[KRB];
__device__ unsigned int  g_ctr;

// ---------------------------------------------------------------------------
__device__ __forceinline__ void mma16816(float* c, const uint32_t* a, uint32_t b0, uint32_t b1)
{
    asm volatile(
        "mma.sync.aligned.m16n8k16.row.col.f32.bf16.bf16.f32 "
        "{%0,%1,%2,%3}, {%4,%5,%6,%7}, {%8,%9}, {%0,%1,%2,%3};\n"
        : "+f"(c[0]), "+f"(c[1]), "+f"(c[2]), "+f"(c[3])
        : "r"(a[0]), "r"(a[1]), "r"(a[2]), "r"(a[3]), "r"(b0), "r"(b1));
}

// cp.async one tile: 128 rows x 256B into padded-272B-stride smem
__device__ __forceinline__ void load_tile_async(uint32_t dstbase, int srcrow, int tid)
{
#pragma unroll
    for (int i = 0; i < 8; i++) {
        int cid = tid + i * 256;
        int row = cid >> 4, ch = cid & 15;
        asm volatile("cp.async.cg.shared.global [%0], [%1], 16;\n"
                     :: "r"(dstbase + (uint32_t)(row * 272 + ch * 16)),
                        "l"((const void*)(&g_cB[srcrow + row][ch * 8])) : "memory");
    }
}

__device__ __forceinline__ int lab_of(int c, const int* label, const int* lq)
{
    int i = (c >= Bn) ? c - Bn : c;
    return (i < BSZh) ? label[i] : ((i < Qn) ? lq[i] : label[i - Qn]);
}

// ---------------------------------------------------------------------------
// Kernel P: gather contrast rows (bf16) + labels. 136 blocks x 64 cols,
// 8 float4 per thread (high MLP). Block 136 builds class buckets.
// ---------------------------------------------------------------------------
__global__ void __launch_bounds__(256) kprep(const float* __restrict__ feat,
                                             const int*   __restrict__ label,
                                             const float* __restrict__ fq,
                                             const float* __restrict__ fq2,
                                             const int*   __restrict__ lq)
{
    if (blockIdx.x == 136) {      // ---- bucket block ----
        __shared__ int scnt[NCLS], soff[NCLS + 1];
        int tid = threadIdx.x;
        if (tid < NCLS) scnt[tid] = 0;
        __syncthreads();
        for (int c = tid; c < N2; c += 256) atomicAdd(&scnt[lab_of(c, label, lq)], 1);
        __syncthreads();
        if (tid == 0) {
            int run = 0;
            for (int k = 0; k < NCLS; k++) { soff[k] = run; run += scnt[k]; }
            soff[NCLS] = run;
            g_ctr = 0u;
        }
        __syncthreads();
        if (tid <= NCLS) g_clsOff[tid] = soff[tid];
        if (tid < NCLS)  scnt[tid] = 0;
        __syncthreads();
        for (int c = tid; c < N2; c += 256) {
            int l = lab_of(c, label, lq);
            int rank = atomicAdd(&scnt[l], 1);
            g_pk[c] = l | (rank << 16);
        }
        return;
    }

    int tid = threadIdx.x;
    int c = blockIdx.x * 64 + (tid >> 2);   // column
    int qq = tid & 3;                       // quarter of the 128 floats
    int half = (c >= Bn) ? 1 : 0;
    int i = c - half * Bn;

    const float* src;
    if (i < BSZh)      src = feat + (half ? i : (BSZh + i)) * Dk;
    else if (i < Qn)   src = (half ? fq2 : fq) + i * Dk;
    else               src = feat + ((half ? BSZh : 0) + (i - Qn)) * Dk;
    src += qq * 32;

    float4 v[8];
#pragma unroll
    for (int j = 0; j < 8; j++) v[j] = *(const float4*)(src + j * 4);
#pragma unroll
    for (int j = 0; j < 8; j++) {
        __nv_bfloat162 b01, b23;
        b01.x = __float2bfloat16(v[j].x); b01.y = __float2bfloat16(v[j].y);
        b23.x = __float2bfloat16(v[j].z); b23.y = __float2bfloat16(v[j].w);
        *(__nv_bfloat162*)(&g_cB[c][qq * 32 + j * 4])     = b01;
        *(__nv_bfloat162*)(&g_cB[c][qq * 32 + j * 4 + 2]) = b23;
    }
    if (qq == 0) g_lab[c] = lab_of(c, label, lq);
}

// ---------------------------------------------------------------------------
// Kernel G: HMMA GEMM, M-tile 128 x N-quarter 2176, K=128.
// Warp tile M=16 x N=128 (R3-proven shape). cp.async double-buffered B.
// Fused masked sum-of-exp + dense positive scatter. grid (34,4) x 256 thr.
// ---------------------------------------------------------------------------
#define SM_A   0                       // 128*272 = 34816
#define SM_B0  34816
#define SM_B1  69632
#define SM_PK  104448                  // 2176*4  = 8704
#define SMEM_BYTES 113152

__global__ void __launch_bounds__(256) kgemm()
{
    extern __shared__ __align__(16) unsigned char sm[];
    const uint32_t smem_base = (uint32_t)__cvta_generic_to_shared(sm);
    int* sPk = (int*)(sm + SM_PK);

    const int tid = threadIdx.x, lane = tid & 31, wid = tid >> 5;
    const int rowbase = blockIdx.x * 128;
    const int colbase = blockIdx.y * COLQ;

    // prologue: A + B0 (group0), B1 (group1), then pk table (plain LDG/STS)
    load_tile_async(smem_base + SM_A,  ROW0 + rowbase, tid);
    load_tile_async(smem_base + SM_B0, colbase, tid);
    asm volatile("cp.async.commit_group;\n" ::: "memory");
    load_tile_async(smem_base + SM_B1, colbase + 128, tid);
    asm volatile("cp.async.commit_group;\n" ::: "memory");
    for (int i = tid; i < COLQ; i += 256) sPk[i] = g_pk[colbase + i];

    // this thread's two rows (within warp's 16-row strip)
    const int r0g = rowbase + wid * 16 + (lane >> 2);
    const int rl0 = g_lab[ROW0 + r0g];
    const int rl1 = g_lab[ROW0 + r0g + 8];
    float z0 = 0.f, z1 = 0.f;

    asm volatile("cp.async.wait_group 1;\n" ::: "memory");
    __syncthreads();

    // preload A fragments once: 8 k-steps x 4 regs
    uint32_t afr[8][4];
    {
        uint32_t a0 = smem_base + SM_A + (wid * 16 + (lane & 15)) * 272 + ((lane >> 4) << 4);
#pragma unroll
        for (int ks = 0; ks < 8; ks++) {
            asm volatile("ldmatrix.sync.aligned.m8n8.x4.shared.b16 {%0,%1,%2,%3}, [%4];"
                         : "=r"(afr[ks][0]), "=r"(afr[ks][1]),
                           "=r"(afr[ks][2]), "=r"(afr[ks][3])
                         : "r"(a0 + ks * 32));
        }
    }
    __syncthreads();

    const int bj = lane >> 3;
    const int bn_off = ((bj & 2) << 2) + (lane & 7);
    const uint32_t bk_off = (uint32_t)((bj & 1) << 4);

    for (int t = 0; t < NTILE; t++) {
        const uint32_t bbase = smem_base + ((t & 1) ? SM_B1 : SM_B0);

        // MMA: 16(M) x 128(N) per warp, K=128
        float acc[16][4] = {};
#pragma unroll
        for (int ks = 0; ks < 8; ks++) {
#pragma unroll
            for (int gix = 0; gix < 8; gix++) {
                uint32_t ba = bbase + (uint32_t)((gix * 16 + bn_off) * 272)
                              + (uint32_t)(ks * 32) + bk_off;
                uint32_t b0, b1, b2, b3;
                asm volatile("ldmatrix.sync.aligned.m8n8.x4.shared.b16 {%0,%1,%2,%3}, [%4];"
                             : "=r"(b0), "=r"(b1), "=r"(b2), "=r"(b3) : "r"(ba));
                mma16816(acc[2 * gix],     afr[ks], b0, b1);
                mma16816(acc[2 * gix + 1], afr[ks], b2, b3);
            }
        }
        __syncthreads();   // all warps done reading buf[t&1]

        // start filling the freed buffer (overlaps epilogue + next MMA)
        if (t + 2 < NTILE) {
            load_tile_async(smem_base + ((t & 1) ? SM_B1 : SM_B0),
                            colbase + (t + 2) * 128, tid);
            asm volatile("cp.async.commit_group;\n" ::: "memory");
        }

        // epilogue: masked sum-of-exp + positive-logit scatter
        const int cb = t * 128 + 2 * (lane & 3);
#pragma unroll
        for (int g2 = 0; g2 < 16; g2++) {
            int col = cb + (g2 >> 1) * 16 + (g2 & 1) * 8;
            int2 pk = *(const int2*)&sPk[col];
            int l0 = pk.x & 0xffff, l1 = pk.y & 0xffff;
            float x00 = acc[g2][0] * INV_T, x01 = acc[g2][1] * INV_T;
            float x10 = acc[g2][2] * INV_T, x11 = acc[g2][3] * INV_T;
            bool e00 = (l0 == rl0), e01 = (l1 == rl0);
            bool e10 = (l0 == rl1), e11 = (l1 == rl1);
            z0 += __expf(e00 ? -2e30f : x00) + __expf(e01 ? -2e30f : x01);
            z1 += __expf(e10 ? -2e30f : x10) + __expf(e11 ? -2e30f : x11);
            if (e00) g_posD[r0g * MAXP + (pk.x >> 16)] = x00;
            if (e01) g_posD[r0g * MAXP + (pk.y >> 16)] = x01;
            if (e10) g_posD[(r0g + 8) * MAXP + (pk.x >> 16)] = x10;
            if (e11) g_posD[(r0g + 8) * MAXP + (pk.y >> 16)] = x11;
        }

        if (t + 2 < NTILE)      asm volatile("cp.async.wait_group 1;\n" ::: "memory");
        else if (t + 2 == NTILE) asm volatile("cp.async.wait_group 0;\n" ::: "memory");
        if (t + 1 < NTILE) __syncthreads();
    }

    // each row is owned by exactly one warp: reduce across the 4 lanes
    z0 += __shfl_xor_sync(0xffffffffu, z0, 1);
    z0 += __shfl_xor_sync(0xffffffffu, z0, 2);
    z1 += __shfl_xor_sync(0xffffffffu, z1, 1);
    z1 += __shfl_xor_sync(0xffffffffu, z1, 2);
    if ((lane & 3) == 0) {
        g_rowZ[r0g][blockIdx.y]     = z0;
        g_rowZ[r0g + 8][blockIdx.y] = z1;
    }
}

// ---------------------------------------------------------------------------
// Kernel R: thread per row over dense positives + fused final mean
// ---------------------------------------------------------------------------
__global__ void __launch_bounds__(128) krow(float* __restrict__ out)
{
    __shared__ float sr[128];
    __shared__ bool amLast;

    int tid = threadIdx.x;
    int w = blockIdx.x * 128 + tid;
    int g = ROW0 + w;
    int rl = g_lab[g];
    bool exc = (g < Bn) || (g == 8192);
    int cnt = g_clsOff[rl + 1] - g_clsOff[rl];
    int selfRank = g_pk[g] >> 16;

    float4 zz = *(const float4*)g_rowZ[w];
    float lse = __logf((zz.x + zz.y) + (zz.z + zz.w));

    float s = 0.f;
    const float* pd = &g_posD[w * MAXP];
#pragma unroll 4
    for (int i = 0; i < cnt; i++) {
        float x = pd[i];
        if (!(exc && i == selfRank)) s += fminf(0.f, x - lse);
    }
    sr[tid] = s / (float)(cnt - (exc ? 1 : 0));
    __syncthreads();
    for (int st = 64; st; st >>= 1) {
        if (tid < st) sr[tid] += sr[tid + st];
        __syncthreads();
    }
    if (tid == 0) {
        g_blkSum[blockIdx.x] = sr[0];
        __threadfence();
        amLast = (atomicAdd(&g_ctr, 1u) == gridDim.x - 1);
    }
    __syncthreads();
    if (amLast && tid == 0) {
        float a = 0.f;
#pragma unroll
        for (int i = 0; i < KRB; i++) a += g_blkSum[i];
        float loss = -(a / (float)NR);
        out[0] = loss; out[1] = loss; out[2] = loss;
    }
}

// ---------------------------------------------------------------------------
extern "C" void kernel_launch(void* const* d_in, const int* in_sizes, int n_in,
                              void* d_out, int out_size)
{
    const float* feat  = (const float*)d_in[0];
    const int*   label = (const int*)d_in[1];
    const float* fq    = (const float*)d_in[2];
    const float* fq2   = (const float*)d_in[3];
    const int*   lq    = (const int*)d_in[4];
    float* out = (float*)d_out;

    cudaFuncSetAttribute(kgemm, cudaFuncAttributeMaxDynamicSharedMemorySize, SMEM_BYTES);

    kprep<<<137, 256>>>(feat, label, fq, fq2, lq);
    kgemm<<<dim3(NR / 128, NQ), 256, SMEM_BYTES>>>();
    krow<<<KRB, 128>>>(out);
}